// round 6
// baseline (speedup 1.0000x reference)
#include <cuda_runtime.h>
#include <cstdint>

#define BB      32
#define NN      8192
#define HH      512
#define K2      256
#define TM      128
#define THREADS 512
#define EPSLN   1e-5f
#define SLOPE   0.2f
#define KC      32
#define NCH     (HH / KC)       // 16 k-chunks
#define NE      10

#define BROW    36                      // 32 tf32 + 4 pad floats (144 B row)
#define ACHUNK  (TM * BROW * 4)         // 18432 B
#define BCHUNK  (K2 * BROW * 4)         // 36864 B
#define SLOT    (ACHUNK + BCHUNK)       // 55296 B
#define NRING   3

// A image: g_A[b][chunk][8192 rows][36]  (tf32 bits as float)
__device__ float g_A[(size_t)BB * NCH * NN * BROW];
// B image: g_W2C[e][chunk][256 rows][36]
__device__ float g_W2C[NE * NCH * K2 * BROW];

// ---------------- main-kernel smem layout (bytes) ----------------
// ring: 3 slots x 55296 (A then B inside each slot)        [0, 165888)
// epilogue C[128][258] = 132096 reuses [0, 132096)
// params (floats) @ 165888 ; mbars after
#define CSTR    258
#define P_OFF   165888u
#define F_B2    0
#define F_G2    256
#define F_BE2   512
#define F_W3    768           // [256][3]
#define F_B3    1536
#define F_END   1540
#define MBF_OFF (P_OFF + F_END * 4)     // 172048: 3 x full
#define MBE_OFF (MBF_OFF + 24)          // 3 x empty
#define SMEM_TOTAL (MBE_OFF + 24)       // 172096

__device__ __forceinline__ uint32_t smem_u32(const void* p) {
    uint32_t a;
    asm("{ .reg .u64 t; cvta.to.shared.u64 t, %1; cvt.u32.u64 %0, t; }" : "=r"(a) : "l"(p));
    return a;
}
__device__ __forceinline__ uint32_t f2tf(float x) {
    uint32_t r; asm("cvt.rna.tf32.f32 %0, %1;" : "=r"(r) : "f"(x)); return r;
}
__device__ __forceinline__ float warp_sum(float v) {
#pragma unroll
    for (int o = 16; o; o >>= 1) v += __shfl_xor_sync(0xffffffffu, v, o);
    return v;
}
__device__ __forceinline__ void ldsm4(uint32_t* r, uint32_t addr) {
    asm volatile("ldmatrix.sync.aligned.m8n8.x4.shared.b16 {%0,%1,%2,%3}, [%4];"
                 : "=r"(r[0]), "=r"(r[1]), "=r"(r[2]), "=r"(r[3]) : "r"(addr));
}
__device__ __forceinline__ void mma_tf32(float* c, const uint32_t* a, uint32_t b0, uint32_t b1) {
    asm volatile("mma.sync.aligned.m16n8k8.row.col.f32.tf32.tf32.f32 "
                 "{%0,%1,%2,%3}, {%4,%5,%6,%7}, {%8,%9}, {%0,%1,%2,%3};"
                 : "+f"(c[0]), "+f"(c[1]), "+f"(c[2]), "+f"(c[3])
                 : "r"(a[0]), "r"(a[1]), "r"(a[2]), "r"(a[3]), "r"(b0), "r"(b1));
}
__device__ __forceinline__ void mbar_wait(uint32_t addr, uint32_t parity) {
    asm volatile(
        "{\n\t.reg .pred P;\n\t"
        "WL_%=:\n\t"
        "mbarrier.try_wait.parity.acquire.cta.shared::cta.b64 P, [%0], %1, 0x989680;\n\t"
        "@P bra.uni WD_%=;\n\t"
        "bra.uni WL_%=;\n\t"
        "WD_%=:\n\t}"
        :: "r"(addr), "r"(parity) : "memory");
}
__device__ __forceinline__ void bulk_in(uint32_t dst, const void* src, uint32_t bytes,
                                        uint32_t mbar) {
    asm volatile(
        "cp.async.bulk.shared::cluster.global.mbarrier::complete_tx::bytes "
        "[%0], [%1], %2, [%3];"
        :: "r"(dst), "l"(src), "r"(bytes), "r"(mbar) : "memory");
}
__device__ __forceinline__ void expect_tx(uint32_t mbar, uint32_t bytes) {
    asm volatile("mbarrier.arrive.expect_tx.shared.b64 _, [%0], %1;"
                 :: "r"(mbar), "r"(bytes) : "memory");
}
__device__ __forceinline__ void mbar_arrive(uint32_t mbar) {
    asm volatile("mbarrier.arrive.shared.b64 _, [%0];" :: "r"(mbar) : "memory");
}

// ------------- W2 pack pre-kernel: transpose + tf32 + chunk image -------------
__global__ void pack_w2(const float* __restrict__ W2) {
    __shared__ float t[32][33];
    const int e  = blockIdx.z;
    const int kb = blockIdx.x * 32, nb = blockIdx.y * 32;
    const int tx = threadIdx.x, ty = threadIdx.y;
    const float* src = W2 + e * HH * K2;
#pragma unroll
    for (int r = 0; r < 32; r += 8)
        t[ty + r][tx] = src[(kb + ty + r) * K2 + nb + tx];
    __syncthreads();
    float* dst = g_W2C + ((size_t)(e * NCH + (kb >> 5)) * K2) * BROW;
#pragma unroll
    for (int r = 0; r < 32; r += 8)
        dst[(nb + ty + r) * BROW + tx] = __uint_as_float(f2tf(t[tx][ty + r]));
}

// ------------- h1 precompute: GEMM1 + LN1 + lrelu + tf32 -> g_A chunk image ----
// 512 threads; CTA = 64 points of one batch; warp handles 4 points.
__global__ __launch_bounds__(512, 2)
void precompute_h1(const float* __restrict__ points, const int* __restrict__ cat,
                   const float* __restrict__ W1, const float* __restrict__ b1,
                   const float* __restrict__ g1, const float* __restrict__ be1)
{
    __shared__ float sw[3 * HH + 3 * HH + 64 * 3];   // W1, (b1,g1,be1), pts
    float* sW1 = sw;                 // [3][512]
    float* sB1 = sw + 3 * HH;        // [512]
    float* sG1 = sB1 + HH;
    float* sE1 = sG1 + HH;
    float* sPt = sE1 + HH;           // [64][3]

    const int tid = threadIdx.x, wid = tid >> 5, lane = tid & 31;
    const int b   = blockIdx.y;
    const int m0  = blockIdx.x * 64;
    const int ci  = cat[b];

    for (int i = tid; i < 3 * HH; i += 512) sW1[i] = W1[ci * 3 * HH + i];
    for (int i = tid; i < HH; i += 512) {
        sB1[i] = b1 [ci * HH + i];
        sG1[i] = g1 [ci * HH + i];
        sE1[i] = be1[ci * HH + i];
    }
    for (int i = tid; i < 64 * 3; i += 512)
        sPt[i] = points[(size_t)(b * NN + m0) * 3 + i];
    __syncthreads();

#pragma unroll 1
    for (int j = 0; j < 4; j++) {
        const int ml = wid * 4 + j;
        const float p0 = sPt[ml * 3 + 0];
        const float p1 = sPt[ml * 3 + 1];
        const float p2 = sPt[ml * 3 + 2];
        float h[16];
        float s = 0.f, s2 = 0.f;
#pragma unroll
        for (int q = 0; q < 4; q++) {
            const int k = lane * 16 + q * 4;
            const float4 a0 = *(const float4*)(sW1 + k);
            const float4 a1 = *(const float4*)(sW1 + HH + k);
            const float4 a2 = *(const float4*)(sW1 + 2 * HH + k);
            const float4 bb = *(const float4*)(sB1 + k);
            h[q*4+0] = fmaf(p0, a0.x, fmaf(p1, a1.x, fmaf(p2, a2.x, bb.x)));
            h[q*4+1] = fmaf(p0, a0.y, fmaf(p1, a1.y, fmaf(p2, a2.y, bb.y)));
            h[q*4+2] = fmaf(p0, a0.z, fmaf(p1, a1.z, fmaf(p2, a2.z, bb.z)));
            h[q*4+3] = fmaf(p0, a0.w, fmaf(p1, a1.w, fmaf(p2, a2.w, bb.w)));
#pragma unroll
            for (int u = 0; u < 4; u++) { s += h[q*4+u]; s2 = fmaf(h[q*4+u], h[q*4+u], s2); }
        }
        s  = warp_sum(s);
        s2 = warp_sum(s2);
        const float mu = s * (1.f / HH);
        const float rs = rsqrtf(s2 * (1.f / HH) - mu * mu + EPSLN);

        const int ch  = lane >> 1;
        const int kk0 = (lane & 1) * 16;
        float* dst = g_A + ((size_t)(b * NCH + ch) * NN + (m0 + ml)) * BROW + kk0;
#pragma unroll
        for (int q = 0; q < 4; q++) {
            const int k = lane * 16 + q * 4;
            const float4 gg = *(const float4*)(sG1 + k);
            const float4 ee = *(const float4*)(sE1 + k);
            float y0 = fmaf((h[q*4+0] - mu) * rs, gg.x, ee.x);
            float y1 = fmaf((h[q*4+1] - mu) * rs, gg.y, ee.y);
            float y2 = fmaf((h[q*4+2] - mu) * rs, gg.z, ee.z);
            float y3 = fmaf((h[q*4+3] - mu) * rs, gg.w, ee.w);
            y0 = y0 >= 0.f ? y0 : SLOPE * y0;
            y1 = y1 >= 0.f ? y1 : SLOPE * y1;
            y2 = y2 >= 0.f ? y2 : SLOPE * y2;
            y3 = y3 >= 0.f ? y3 : SLOPE * y3;
            uint4 v = make_uint4(f2tf(y0), f2tf(y1), f2tf(y2), f2tf(y3));
            *(uint4*)(dst + q * 4) = v;
        }
    }
}

extern __shared__ char smem_raw[];

__global__ __launch_bounds__(THREADS, 1)
void shape_prior_mma(const int* __restrict__ cat,
                     const float* __restrict__ b2, const float* __restrict__ g2,
                     const float* __restrict__ be2,
                     const float* __restrict__ W3, const float* __restrict__ b3,
                     float* __restrict__ out)
{
    float* pf  = (float*)(smem_raw + P_OFF);
    float* csm = (float*)smem_raw;
    const int tid  = threadIdx.x;
    const int wid  = tid >> 5;
    const int lane = tid & 31;
    const int bIdx = blockIdx.y;
    const int m0   = blockIdx.x * TM;
    const int ci   = cat[bIdx];
    const uint32_t sbase = smem_u32(smem_raw);

    // ---- stage epilogue params ----
    for (int i = tid; i < K2; i += THREADS) {
        pf[F_B2  + i] = b2 [ci * K2 + i];
        pf[F_G2  + i] = g2 [ci * K2 + i];
        pf[F_BE2 + i] = be2[ci * K2 + i];
    }
    for (int i = tid; i < K2 * 3; i += THREADS) pf[F_W3 + i] = W3[ci * K2 * 3 + i];
    if (tid < 3) pf[F_B3 + tid] = b3[ci * 3 + tid];
    if (tid == 0) {
#pragma unroll
        for (int j = 0; j < NRING; j++) {
            asm volatile("mbarrier.init.shared.b64 [%0], 1;"
                         :: "r"(sbase + MBF_OFF + 8u * j) : "memory");
            asm volatile("mbarrier.init.shared.b64 [%0], 16;"
                         :: "r"(sbase + MBE_OFF + 8u * j) : "memory");
        }
    }
    __syncthreads();

    const float* Asrc = g_A   + ((size_t)bIdx * NCH * NN + m0) * BROW;   // + c*NN*BROW
    const float* Bsrc = g_W2C + (size_t)ci * NCH * K2 * BROW;            // + c*K2*BROW

    // kick off chunks 0,1 (slots 0,1)
    if (tid == 0) {
#pragma unroll
        for (int j = 0; j < 2; j++) {
            const uint32_t mb = sbase + MBF_OFF + 8u * j;
            expect_tx(mb, SLOT);
            bulk_in(sbase + (uint32_t)SLOT * j,
                    Asrc + (size_t)j * NN * BROW, ACHUNK, mb);
            bulk_in(sbase + (uint32_t)SLOT * j + ACHUNK,
                    Bsrc + (size_t)j * K2 * BROW, BCHUNK, mb);
        }
    }

    // warp tile: wm = wid>>2 (rows wm*32..), wn = wid&3 (cols wn*64..)
    const int wm = wid >> 2, wn = wid & 3;
    const int grp = lane >> 3, r8 = lane & 7;
    const uint32_t a_lane = (uint32_t)((r8 + ((grp & 1) << 3)) * 144 + (grp >> 1) * 16)
                          + (uint32_t)(wm * 32 * 144);
    const uint32_t b_lane = (uint32_t)((r8 + ((grp >> 1) << 3)) * 144 + (grp & 1) * 16)
                          + (uint32_t)(wn * 64 * 144) + ACHUNK;

    float acc[64];
#pragma unroll
    for (int i = 0; i < 64; i++) acc[i] = 0.f;

#pragma unroll 1
    for (int c = 0; c < NCH; c++) {
        const int slot = c % 3, pass = c / 3;
        // producer: stage chunk c+2
        if (tid == 0) {
            const int f = c + 2;
            if (f < NCH) {
                const int sf = f % 3, pfs = f / 3;
                if (pfs > 0) mbar_wait(sbase + MBE_OFF + 8u * sf, (uint32_t)((pfs - 1) & 1));
                const uint32_t mb = sbase + MBF_OFF + 8u * sf;
                expect_tx(mb, SLOT);
                bulk_in(sbase + (uint32_t)SLOT * sf,
                        Asrc + (size_t)f * NN * BROW, ACHUNK, mb);
                bulk_in(sbase + (uint32_t)SLOT * sf + ACHUNK,
                        Bsrc + (size_t)f * K2 * BROW, BCHUNK, mb);
            }
        }
        mbar_wait(sbase + MBF_OFF + 8u * slot, (uint32_t)(pass & 1));

        const uint32_t sb = sbase + (uint32_t)SLOT * slot;
#pragma unroll
        for (int ks = 0; ks < 4; ks++) {
            const uint32_t koff = (uint32_t)(ks * 32);
            uint32_t af[2][4], bf[4][4];
#pragma unroll
            for (int mt = 0; mt < 2; mt++)
                ldsm4(af[mt], sb + a_lane + (uint32_t)(mt * 2304) + koff);
#pragma unroll
            for (int p = 0; p < 4; p++)
                ldsm4(bf[p], sb + b_lane + (uint32_t)(p * 2304) + koff);
#pragma unroll
            for (int mt = 0; mt < 2; mt++)
#pragma unroll
                for (int p = 0; p < 4; p++) {
                    mma_tf32(&acc[mt * 32 + (2 * p) * 4],     af[mt], bf[p][0], bf[p][1]);
                    mma_tf32(&acc[mt * 32 + (2 * p + 1) * 4], af[mt], bf[p][2], bf[p][3]);
                }
        }
        if (lane == 0) mbar_arrive(sbase + MBE_OFF + 8u * slot);
    }
    __syncthreads();   // all warps done before overwriting ring with C

    // ---- store acc to smem C [128][CSTR] ----
    {
        const int rbase = wm * 32 + (lane >> 2);
        const int cbase = wn * 64 + 2 * (lane & 3);
#pragma unroll
        for (int mt = 0; mt < 2; mt++)
#pragma unroll
            for (int nt = 0; nt < 8; nt++) {
                const float* a4 = &acc[mt * 32 + nt * 4];
                const int r0 = rbase + mt * 16, cc = cbase + nt * 8;
                *(float2*)(csm + r0 * CSTR + cc)       = make_float2(a4[0], a4[1]);
                *(float2*)(csm + (r0 + 8) * CSTR + cc) = make_float2(a4[2], a4[3]);
            }
    }
    __syncthreads();

    // ---- epilogue: bias2 + LN2 + lrelu + GEMM3 (N=3); 16 warps x 8 rows ----
#pragma unroll 1
    for (int rr = 0; rr < 8; rr++) {
        const int m = wid * 8 + rr;
        float fv[8];
        float s = 0.f, s2 = 0.f;
#pragma unroll
        for (int j = 0; j < 8; j++) {
            const int n = lane + 32 * j;
            fv[j] = csm[m * CSTR + n] + pf[F_B2 + n];
            s += fv[j];
            s2 = fmaf(fv[j], fv[j], s2);
        }
        s  = warp_sum(s);
        s2 = warp_sum(s2);
        const float mu  = s * (1.f / K2);
        const float inv = rsqrtf(s2 * (1.f / K2) - mu * mu + EPSLN);
        float o0 = 0.f, o1 = 0.f, o2 = 0.f;
#pragma unroll
        for (int j = 0; j < 8; j++) {
            const int n = lane + 32 * j;
            float y = (fv[j] - mu) * inv * pf[F_G2 + n] + pf[F_BE2 + n];
            y = y >= 0.f ? y : SLOPE * y;
            o0 = fmaf(y, pf[F_W3 + n * 3 + 0], o0);
            o1 = fmaf(y, pf[F_W3 + n * 3 + 1], o1);
            o2 = fmaf(y, pf[F_W3 + n * 3 + 2], o2);
        }
        o0 = warp_sum(o0); o1 = warp_sum(o1); o2 = warp_sum(o2);
        if (lane == 0) {
            float* op = out + (size_t)(bIdx * NN + m0 + m) * 3;
            op[0] = o0 + pf[F_B3 + 0];
            op[1] = o1 + pf[F_B3 + 1];
            op[2] = o2 + pf[F_B3 + 2];
        }
    }
}

extern "C" void kernel_launch(void* const* d_in, const int* in_sizes, int n_in,
                              void* d_out, int out_size)
{
    const float* points = (const float*)d_in[0];
    const int*   cat    = (const int*)  d_in[1];
    const float* W1     = (const float*)d_in[2];
    const float* b1     = (const float*)d_in[3];
    const float* g1     = (const float*)d_in[4];
    const float* be1    = (const float*)d_in[5];
    const float* W2     = (const float*)d_in[6];
    const float* b2     = (const float*)d_in[7];
    const float* g2     = (const float*)d_in[8];
    const float* be2    = (const float*)d_in[9];
    const float* W3     = (const float*)d_in[10];
    const float* b3     = (const float*)d_in[11];
    float* out = (float*)d_out;

    cudaFuncSetAttribute(shape_prior_mma,
                         cudaFuncAttributeMaxDynamicSharedMemorySize, SMEM_TOTAL);

    pack_w2<<<dim3(HH / 32, K2 / 32, NE), dim3(32, 8)>>>(W2);
    precompute_h1<<<dim3(NN / 64, BB), 512>>>(points, cat, W1, b1, g1, be1);
    shape_prior_mma<<<dim3(NN / TM, BB), THREADS, SMEM_TOTAL>>>(
        cat, b2, g2, be2, W3, b3, out);
}

// round 7
// speedup vs baseline: 1.2017x; 1.2017x over previous
#include <cuda_runtime.h>
#include <cuda_fp16.h>
#include <cstdint>

#define BB      32
#define NN      8192
#define HH      512
#define K2      256
#define TM      128
#define THREADS 512
#define EPSLN   1e-5f
#define SLOPE   0.2f
#define KC      64
#define NCH     (HH / KC)       // 8 k-chunks
#define NE      10

// Row: 64 fp16 (128 B) + 16 B pad = 144 B  (72 halves)
#define BROWH   72
#define ACHUNK  (TM * 144)              // 18432 B
#define BCHUNK  (K2 * 144)              // 36864 B

// Packed fp16 W2 chunks: g_W2C[e][chunk][n (256)][72 halves]
__device__ __half g_W2C[(size_t)NE * NCH * K2 * BROWH];

// ---------------- smem layout (bytes) ----------------
//   A0 @ 0       (128 x 144 = 18432)
//   A1 @ 18432
//   B ring: 4 x 36864 @ 36864          (ends 184320)
// Epilogue C[128][258] (132096 B) reuses [0, 132096)
#define A0_OFF 0u
#define A1_OFF 18432u
#define B0_OFF 36864u
#define CSTR   258
#define P_OFF  184320u
#define F_W1    0             // [3][512]
#define F_B1    1536
#define F_G1    2048
#define F_BE1   2560
#define F_B2    3072
#define F_G2    3328
#define F_BE2   3584
#define F_W3    3840          // [256][3]
#define F_B3    4608
#define F_PTS   4612          // [128][3]
#define F_MU    4996
#define F_RS    5124
#define F_END   5252
#define MB_OFF  (P_OFF + F_END * 4)    // 4 x 8B mbarriers
#define SMEM_TOTAL (MB_OFF + 32)

__device__ __forceinline__ uint32_t smem_u32(const void* p) {
    uint32_t a;
    asm("{ .reg .u64 t; cvta.to.shared.u64 t, %1; cvt.u32.u64 %0, t; }" : "=r"(a) : "l"(p));
    return a;
}
__device__ __forceinline__ float warp_sum(float v) {
#pragma unroll
    for (int o = 16; o; o >>= 1) v += __shfl_xor_sync(0xffffffffu, v, o);
    return v;
}
__device__ __forceinline__ void ldsm4(uint32_t* r, uint32_t addr) {
    asm volatile("ldmatrix.sync.aligned.m8n8.x4.shared.b16 {%0,%1,%2,%3}, [%4];"
                 : "=r"(r[0]), "=r"(r[1]), "=r"(r[2]), "=r"(r[3]) : "r"(addr));
}
__device__ __forceinline__ void mma_f16(float* c, const uint32_t* a, uint32_t b0, uint32_t b1) {
    asm volatile("mma.sync.aligned.m16n8k16.row.col.f32.f16.f16.f32 "
                 "{%0,%1,%2,%3}, {%4,%5,%6,%7}, {%8,%9}, {%0,%1,%2,%3};"
                 : "+f"(c[0]), "+f"(c[1]), "+f"(c[2]), "+f"(c[3])
                 : "r"(a[0]), "r"(a[1]), "r"(a[2]), "r"(a[3]), "r"(b0), "r"(b1));
}
__device__ __forceinline__ void mbar_wait(uint32_t addr, uint32_t parity) {
    asm volatile(
        "{\n\t.reg .pred P;\n\t"
        "WL_%=:\n\t"
        "mbarrier.try_wait.parity.acquire.cta.shared::cta.b64 P, [%0], %1, 0x989680;\n\t"
        "@P bra.uni WD_%=;\n\t"
        "bra.uni WL_%=;\n\t"
        "WD_%=:\n\t}"
        :: "r"(addr), "r"(parity) : "memory");
}
__device__ __forceinline__ void bulk_in(uint32_t dst, const void* src, uint32_t bytes,
                                        uint32_t mbar) {
    asm volatile(
        "cp.async.bulk.shared::cluster.global.mbarrier::complete_tx::bytes "
        "[%0], [%1], %2, [%3];"
        :: "r"(dst), "l"(src), "r"(bytes), "r"(mbar) : "memory");
}
__device__ __forceinline__ void expect_tx(uint32_t mbar, uint32_t bytes) {
    asm volatile("mbarrier.arrive.expect_tx.shared.b64 _, [%0], %1;"
                 :: "r"(mbar), "r"(bytes) : "memory");
}

// ------------- W2 pack pre-kernel: transpose + fp16 + chunk image -------------
__global__ void pack_w2(const float* __restrict__ W2) {
    __shared__ float t[32][33];
    const int e  = blockIdx.z;
    const int kb = blockIdx.x * 32, nb = blockIdx.y * 32;
    const int tx = threadIdx.x, ty = threadIdx.y;
    const float* src = W2 + e * HH * K2;
#pragma unroll
    for (int r = 0; r < 32; r += 8)
        t[ty + r][tx] = src[(kb + ty + r) * K2 + nb + tx];
    __syncthreads();
    const int ch = kb >> 6, k0 = kb & 63;
    __half* dst = g_W2C + ((size_t)(e * NCH + ch) * K2) * BROWH;
#pragma unroll
    for (int r = 0; r < 32; r += 8)
        dst[(size_t)(nb + ty + r) * BROWH + k0 + tx] = __float2half_rn(t[tx][ty + r]);
}

extern __shared__ char smem_raw[];

__global__ __launch_bounds__(THREADS, 1)
void shape_prior_mma(const float* __restrict__ points, const int* __restrict__ cat,
                     const float* __restrict__ W1, const float* __restrict__ b1,
                     const float* __restrict__ g1, const float* __restrict__ be1,
                     const float* __restrict__ b2, const float* __restrict__ g2,
                     const float* __restrict__ be2,
                     const float* __restrict__ W3, const float* __restrict__ b3,
                     float* __restrict__ out)
{
    float* pf  = (float*)(smem_raw + P_OFF);
    float* csm = (float*)smem_raw;
    const int tid  = threadIdx.x;
    const int wid  = tid >> 5;
    const int lane = tid & 31;
    const int bIdx = blockIdx.y;
    const int m0   = blockIdx.x * TM;
    const int ci   = cat[bIdx];
    const uint32_t sbase = smem_u32(smem_raw);

    // ---- stage per-expert params + points ----
    for (int i = tid; i < 3 * HH; i += THREADS) pf[F_W1 + i] = W1[ci * 3 * HH + i];
    for (int i = tid; i < HH; i += THREADS) {
        pf[F_B1  + i] = b1 [ci * HH + i];
        pf[F_G1  + i] = g1 [ci * HH + i];
        pf[F_BE1 + i] = be1[ci * HH + i];
    }
    for (int i = tid; i < K2; i += THREADS) {
        pf[F_B2  + i] = b2 [ci * K2 + i];
        pf[F_G2  + i] = g2 [ci * K2 + i];
        pf[F_BE2 + i] = be2[ci * K2 + i];
    }
    for (int i = tid; i < K2 * 3; i += THREADS) pf[F_W3 + i] = W3[ci * K2 * 3 + i];
    if (tid < 3) pf[F_B3 + tid] = b3[ci * 3 + tid];
    for (int i = tid; i < TM * 3; i += THREADS)
        pf[F_PTS + i] = points[(size_t)(bIdx * NN + m0) * 3 + i];
    if (tid == 0) {
#pragma unroll
        for (int j = 0; j < 4; j++)
            asm volatile("mbarrier.init.shared.b64 [%0], 1;"
                         :: "r"(sbase + MB_OFF + 8u * j) : "memory");
    }
    __syncthreads();

    const __half* Wsrc = g_W2C + (size_t)ci * NCH * K2 * BROWH;
    // kick off B chunks 0..2 (prefetch distance 3)
    if (tid == 0) {
#pragma unroll
        for (int j = 0; j < 3; j++) {
            const uint32_t mb = sbase + MB_OFF + 8u * j;
            expect_tx(mb, BCHUNK);
            bulk_in(sbase + B0_OFF + (uint32_t)BCHUNK * j,
                    Wsrc + (size_t)j * K2 * BROWH, BCHUNK, mb);
        }
    }

    // ---- pass 1: per-point LN1 stats (mu, rstd); 16 warps x 8 points ----
#pragma unroll 1
    for (int p = 0; p < 8; p++) {
        const int m = wid * 8 + p;
        const float p0 = pf[F_PTS + m * 3 + 0];
        const float p1 = pf[F_PTS + m * 3 + 1];
        const float p2 = pf[F_PTS + m * 3 + 2];
        float s = 0.f, s2 = 0.f;
#pragma unroll
        for (int q = 0; q < 4; q++) {
            const int k = lane * 16 + q * 4;
            const float4 a0 = *(const float4*)(pf + F_W1 + k);
            const float4 a1 = *(const float4*)(pf + F_W1 + 512 + k);
            const float4 a2 = *(const float4*)(pf + F_W1 + 1024 + k);
            const float4 bb = *(const float4*)(pf + F_B1 + k);
            const float h0 = fmaf(p0, a0.x, fmaf(p1, a1.x, fmaf(p2, a2.x, bb.x)));
            const float h1v= fmaf(p0, a0.y, fmaf(p1, a1.y, fmaf(p2, a2.y, bb.y)));
            const float h2 = fmaf(p0, a0.z, fmaf(p1, a1.z, fmaf(p2, a2.z, bb.z)));
            const float h3 = fmaf(p0, a0.w, fmaf(p1, a1.w, fmaf(p2, a2.w, bb.w)));
            s += h0 + h1v + h2 + h3;
            s2 = fmaf(h0, h0, s2); s2 = fmaf(h1v, h1v, s2);
            s2 = fmaf(h2, h2, s2); s2 = fmaf(h3, h3, s2);
        }
        s  = warp_sum(s);
        s2 = warp_sum(s2);
        if (lane == 0) {
            const float mu = s * (1.f / HH);
            pf[F_MU + m] = mu;
            pf[F_RS + m] = rsqrtf(s2 * (1.f / HH) - mu * mu + EPSLN);
        }
    }
    __syncthreads();

    // A producer: thread covers (m = tid/4, k-quarter = (tid&3)*16 halves)
    const int am = tid >> 2, aq = (tid & 3) * 16;
    const float AP0 = pf[F_PTS + am * 3 + 0];
    const float AP1 = pf[F_PTS + am * 3 + 1];
    const float AP2 = pf[F_PTS + am * 3 + 2];
    const float AMU = pf[F_MU + am];
    const float ARS = pf[F_RS + am];
    const uint32_t a_prod_off = (uint32_t)(am * 144 + (tid & 3) * 32);

    // warp tile: wm = wid>>2 (rows wm*32..), wn = wid&3 (cols wn*64..)
    const int wm = wid >> 2, wn = wid & 3;
    const int grp = lane >> 3, r8 = lane & 7;
    const uint32_t a_lane = (uint32_t)((r8 + ((grp & 1) << 3)) * 144 + (grp >> 1) * 16)
                          + (uint32_t)(wm * 32 * 144);
    const uint32_t b_lane = (uint32_t)((r8 + ((grp >> 1) << 3)) * 144 + (grp & 1) * 16)
                          + (uint32_t)(wn * 64 * 144);

    float acc[64];
#pragma unroll
    for (int i = 0; i < 64; i++) acc[i] = 0.f;

    auto produce_A = [&](int c, uint32_t abuf_off) {
        const uint32_t base = sbase + abuf_off + a_prod_off;
        uint32_t u[8];
#pragma unroll
        for (int q = 0; q < 4; q++) {
            const int k = c * KC + aq + q * 4;
            const float4 a0 = *(const float4*)(pf + F_W1 + k);
            const float4 a1 = *(const float4*)(pf + F_W1 + 512 + k);
            const float4 a2 = *(const float4*)(pf + F_W1 + 1024 + k);
            const float4 bbv= *(const float4*)(pf + F_B1 + k);
            const float4 gg = *(const float4*)(pf + F_G1 + k);
            const float4 ee = *(const float4*)(pf + F_BE1 + k);
            float y0 = (fmaf(AP0, a0.x, fmaf(AP1, a1.x, fmaf(AP2, a2.x, bbv.x))) - AMU) * ARS;
            float y1 = (fmaf(AP0, a0.y, fmaf(AP1, a1.y, fmaf(AP2, a2.y, bbv.y))) - AMU) * ARS;
            float y2 = (fmaf(AP0, a0.z, fmaf(AP1, a1.z, fmaf(AP2, a2.z, bbv.z))) - AMU) * ARS;
            float y3 = (fmaf(AP0, a0.w, fmaf(AP1, a1.w, fmaf(AP2, a2.w, bbv.w))) - AMU) * ARS;
            y0 = fmaf(y0, gg.x, ee.x); y1 = fmaf(y1, gg.y, ee.y);
            y2 = fmaf(y2, gg.z, ee.z); y3 = fmaf(y3, gg.w, ee.w);
            y0 = y0 >= 0.f ? y0 : SLOPE * y0;
            y1 = y1 >= 0.f ? y1 : SLOPE * y1;
            y2 = y2 >= 0.f ? y2 : SLOPE * y2;
            y3 = y3 >= 0.f ? y3 : SLOPE * y3;
            const __half2 h01 = __floats2half2_rn(y0, y1);
            const __half2 h23 = __floats2half2_rn(y2, y3);
            u[q * 2 + 0] = *(const uint32_t*)&h01;
            u[q * 2 + 1] = *(const uint32_t*)&h23;
        }
        asm volatile("st.shared.v4.b32 [%0], {%1,%2,%3,%4};"
                     :: "r"(base), "r"(u[0]), "r"(u[1]), "r"(u[2]), "r"(u[3]));
        asm volatile("st.shared.v4.b32 [%0], {%1,%2,%3,%4};"
                     :: "r"(base + 16u), "r"(u[4]), "r"(u[5]), "r"(u[6]), "r"(u[7]));
    };

    produce_A(0, A0_OFF);

#pragma unroll 1
    for (int c = 0; c < NCH; c++) {
        __syncthreads();   // A(c) visible; mma(c-1) ldsm done -> safe to refill
        if (tid == 0 && c + 3 < NCH) {
            const uint32_t mb = sbase + MB_OFF + 8u * ((c + 3) & 3);
            expect_tx(mb, BCHUNK);
            bulk_in(sbase + B0_OFF + (uint32_t)BCHUNK * ((c + 3) & 3),
                    Wsrc + (size_t)(c + 3) * K2 * BROWH, BCHUNK, mb);
        }
        mbar_wait(sbase + MB_OFF + 8u * (c & 3), (c >> 2) & 1);
        if (c < NCH - 1) produce_A(c + 1, (c & 1) ? A0_OFF : A1_OFF);

        const uint32_t abuf = sbase + ((c & 1) ? A1_OFF : A0_OFF);
        const uint32_t bbuf = sbase + B0_OFF + (uint32_t)BCHUNK * (c & 3);
#pragma unroll
        for (int ks = 0; ks < 4; ks++) {      // k16 steps: 32 B each
            const uint32_t koff = (uint32_t)(ks * 32);
            uint32_t af[2][4], bf[4][4];
#pragma unroll
            for (int mt = 0; mt < 2; mt++)
                ldsm4(af[mt], abuf + a_lane + (uint32_t)(mt * 2304) + koff);
#pragma unroll
            for (int p = 0; p < 4; p++)
                ldsm4(bf[p], bbuf + b_lane + (uint32_t)(p * 2304) + koff);
#pragma unroll
            for (int mt = 0; mt < 2; mt++)
#pragma unroll
                for (int p = 0; p < 4; p++) {
                    mma_f16(&acc[mt * 32 + (2 * p) * 4],     af[mt], bf[p][0], bf[p][1]);
                    mma_f16(&acc[mt * 32 + (2 * p + 1) * 4], af[mt], bf[p][2], bf[p][3]);
                }
        }
    }
    __syncthreads();   // all mma done before overwriting buffers with C

    // ---- store acc to smem C [128][CSTR] ----
    {
        const int rbase = wm * 32 + (lane >> 2);
        const int cbase = wn * 64 + 2 * (lane & 3);
#pragma unroll
        for (int mt = 0; mt < 2; mt++)
#pragma unroll
            for (int nt = 0; nt < 8; nt++) {
                const float* a4 = &acc[mt * 32 + nt * 4];
                const int r0 = rbase + mt * 16, cc = cbase + nt * 8;
                *(float2*)(csm + r0 * CSTR + cc)       = make_float2(a4[0], a4[1]);
                *(float2*)(csm + (r0 + 8) * CSTR + cc) = make_float2(a4[2], a4[3]);
            }
    }
    __syncthreads();

    // ---- epilogue: bias2 + LN2 + lrelu + GEMM3 (N=3); 16 warps x 8 rows ----
#pragma unroll 1
    for (int rr = 0; rr < 8; rr++) {
        const int m = wid * 8 + rr;
        float fv[8];
        float s = 0.f, s2 = 0.f;
#pragma unroll
        for (int j = 0; j < 8; j++) {
            const int n = lane + 32 * j;
            fv[j] = csm[m * CSTR + n] + pf[F_B2 + n];
            s += fv[j];
            s2 = fmaf(fv[j], fv[j], s2);
        }
        s  = warp_sum(s);
        s2 = warp_sum(s2);
        const float mu  = s * (1.f / K2);
        const float inv = rsqrtf(s2 * (1.f / K2) - mu * mu + EPSLN);
        float o0 = 0.f, o1 = 0.f, o2 = 0.f;
#pragma unroll
        for (int j = 0; j < 8; j++) {
            const int n = lane + 32 * j;
            float y = (fv[j] - mu) * inv * pf[F_G2 + n] + pf[F_BE2 + n];
            y = y >= 0.f ? y : SLOPE * y;
            o0 = fmaf(y, pf[F_W3 + n * 3 + 0], o0);
            o1 = fmaf(y, pf[F_W3 + n * 3 + 1], o1);
            o2 = fmaf(y, pf[F_W3 + n * 3 + 2], o2);
        }
        o0 = warp_sum(o0); o1 = warp_sum(o1); o2 = warp_sum(o2);
        if (lane == 0) {
            float* op = out + (size_t)(bIdx * NN + m0 + m) * 3;
            op[0] = o0 + pf[F_B3 + 0];
            op[1] = o1 + pf[F_B3 + 1];
            op[2] = o2 + pf[F_B3 + 2];
        }
    }
}

extern "C" void kernel_launch(void* const* d_in, const int* in_sizes, int n_in,
                              void* d_out, int out_size)
{
    const float* points = (const float*)d_in[0];
    const int*   cat    = (const int*)  d_in[1];
    const float* W1     = (const float*)d_in[2];
    const float* b1     = (const float*)d_in[3];
    const float* g1     = (const float*)d_in[4];
    const float* be1    = (const float*)d_in[5];
    const float* W2     = (const float*)d_in[6];
    const float* b2     = (const float*)d_in[7];
    const float* g2     = (const float*)d_in[8];
    const float* be2    = (const float*)d_in[9];
    const float* W3     = (const float*)d_in[10];
    const float* b3     = (const float*)d_in[11];
    float* out = (float*)d_out;

    cudaFuncSetAttribute(shape_prior_mma,
                         cudaFuncAttributeMaxDynamicSharedMemorySize, SMEM_TOTAL);

    pack_w2<<<dim3(HH / 32, K2 / 32, NE), dim3(32, 8)>>>(W2);
    shape_prior_mma<<<dim3(NN / TM, BB), THREADS, SMEM_TOTAL>>>(
        points, cat, W1, b1, g1, be1, b2, g2, be2, W3, b3, out);
}

// round 8
// speedup vs baseline: 1.2452x; 1.0362x over previous
#include <cuda_runtime.h>
#include <cuda_fp16.h>
#include <cstdint>

#define BB      32
#define NN      8192
#define HH      512
#define K2      256
#define TM      128
#define THREADS 512
#define EPSLN   1e-5f
#define SLOPE   0.2f
#define KC      64
#define NCH     (HH / KC)       // 8 k-chunks
#define NE      10

// B row: 64 fp16 (128 B) + 16 B pad = 144 B (72 halves)
#define BROWH   72
#define BCHUNK  (K2 * 144)              // 36864 B per chunk

// A tile in smem: 128 rows x (512 fp16 = 1024 B + 16 pad) = 1040 B stride
#define AROWB   1040
#define A_SIZE  (TM * AROWB)            // 133120 B

// Packed fp16 W2 chunks: g_W2C[e][chunk][n (256)][72 halves]
__device__ __half g_W2C[(size_t)NE * NCH * K2 * BROWH];

// ---------------- smem layout (bytes) ----------------
//   A      @ 0            133120
//   B ring @ 133120       2 x 36864 -> ends 206848
//   params @ 206848       (floats)
//   mbars  after
// Epilogue C[128][258] (132096 B) reuses [0, 132096)
#define A_OFF  0u
#define B0_OFF 133120u
#define CSTR   258
#define P_OFF  206848u
#define F_W1    0             // [3][512]
#define F_B1    1536
#define F_G1    2048
#define F_BE1   2560
#define F_B2    3072
#define F_G2    3328
#define F_BE2   3584
#define F_W3    3840          // [256][3]
#define F_B3    4608
#define F_PTS   4612          // [128][3]
#define F_MU    4996
#define F_RS    5124
#define F_END   5252
#define MBF_OFF (P_OFF + F_END * 4)    // 2 x full
#define MBE_OFF (MBF_OFF + 16)         // 2 x empty
#define SMEM_TOTAL (MBE_OFF + 16)      // 227888 B  (< 232448 limit)

__device__ __forceinline__ uint32_t smem_u32(const void* p) {
    uint32_t a;
    asm("{ .reg .u64 t; cvta.to.shared.u64 t, %1; cvt.u32.u64 %0, t; }" : "=r"(a) : "l"(p));
    return a;
}
__device__ __forceinline__ float warp_sum(float v) {
#pragma unroll
    for (int o = 16; o; o >>= 1) v += __shfl_xor_sync(0xffffffffu, v, o);
    return v;
}
__device__ __forceinline__ void ldsm4(uint32_t* r, uint32_t addr) {
    asm volatile("ldmatrix.sync.aligned.m8n8.x4.shared.b16 {%0,%1,%2,%3}, [%4];"
                 : "=r"(r[0]), "=r"(r[1]), "=r"(r[2]), "=r"(r[3]) : "r"(addr));
}
__device__ __forceinline__ void mma_f16(float* c, const uint32_t* a, uint32_t b0, uint32_t b1) {
    asm volatile("mma.sync.aligned.m16n8k16.row.col.f32.f16.f16.f32 "
                 "{%0,%1,%2,%3}, {%4,%5,%6,%7}, {%8,%9}, {%0,%1,%2,%3};"
                 : "+f"(c[0]), "+f"(c[1]), "+f"(c[2]), "+f"(c[3])
                 : "r"(a[0]), "r"(a[1]), "r"(a[2]), "r"(a[3]), "r"(b0), "r"(b1));
}
__device__ __forceinline__ void mbar_wait(uint32_t addr, uint32_t parity) {
    asm volatile(
        "{\n\t.reg .pred P;\n\t"
        "WL_%=:\n\t"
        "mbarrier.try_wait.parity.acquire.cta.shared::cta.b64 P, [%0], %1, 0x989680;\n\t"
        "@P bra.uni WD_%=;\n\t"
        "bra.uni WL_%=;\n\t"
        "WD_%=:\n\t}"
        :: "r"(addr), "r"(parity) : "memory");
}
__device__ __forceinline__ void bulk_in(uint32_t dst, const void* src, uint32_t bytes,
                                        uint32_t mbar) {
    asm volatile(
        "cp.async.bulk.shared::cluster.global.mbarrier::complete_tx::bytes "
        "[%0], [%1], %2, [%3];"
        :: "r"(dst), "l"(src), "r"(bytes), "r"(mbar) : "memory");
}
__device__ __forceinline__ void expect_tx(uint32_t mbar, uint32_t bytes) {
    asm volatile("mbarrier.arrive.expect_tx.shared.b64 _, [%0], %1;"
                 :: "r"(mbar), "r"(bytes) : "memory");
}
__device__ __forceinline__ void mbar_arrive(uint32_t mbar) {
    asm volatile("mbarrier.arrive.shared.b64 _, [%0];" :: "r"(mbar) : "memory");
}

// ------------- W2 pack pre-kernel: transpose + fp16 + chunk image -------------
__global__ void pack_w2(const float* __restrict__ W2) {
    __shared__ float t[32][33];
    const int e  = blockIdx.z;
    const int kb = blockIdx.x * 32, nb = blockIdx.y * 32;
    const int tx = threadIdx.x, ty = threadIdx.y;
    const float* src = W2 + e * HH * K2;
#pragma unroll
    for (int r = 0; r < 32; r += 8)
        t[ty + r][tx] = src[(kb + ty + r) * K2 + nb + tx];
    __syncthreads();
    const int ch = kb >> 6, k0 = kb & 63;
    __half* dst = g_W2C + ((size_t)(e * NCH + ch) * K2) * BROWH;
#pragma unroll
    for (int r = 0; r < 32; r += 8)
        dst[(size_t)(nb + ty + r) * BROWH + k0 + tx] = __float2half_rn(t[tx][ty + r]);
}

extern __shared__ char smem_raw[];

__global__ __launch_bounds__(THREADS, 1)
void shape_prior_mma(const float* __restrict__ points, const int* __restrict__ cat,
                     const float* __restrict__ W1, const float* __restrict__ b1,
                     const float* __restrict__ g1, const float* __restrict__ be1,
                     const float* __restrict__ b2, const float* __restrict__ g2,
                     const float* __restrict__ be2,
                     const float* __restrict__ W3, const float* __restrict__ b3,
                     float* __restrict__ out)
{
    float* pf  = (float*)(smem_raw + P_OFF);
    float* csm = (float*)smem_raw;
    const int tid  = threadIdx.x;
    const int wid  = tid >> 5;
    const int lane = tid & 31;
    const int bIdx = blockIdx.y;
    const int m0   = blockIdx.x * TM;
    const int ci   = cat[bIdx];
    const uint32_t sbase = smem_u32(smem_raw);

    // ---- stage per-expert params + points ----
    for (int i = tid; i < 3 * HH; i += THREADS) pf[F_W1 + i] = W1[ci * 3 * HH + i];
    for (int i = tid; i < HH; i += THREADS) {
        pf[F_B1  + i] = b1 [ci * HH + i];
        pf[F_G1  + i] = g1 [ci * HH + i];
        pf[F_BE1 + i] = be1[ci * HH + i];
    }
    for (int i = tid; i < K2; i += THREADS) {
        pf[F_B2  + i] = b2 [ci * K2 + i];
        pf[F_G2  + i] = g2 [ci * K2 + i];
        pf[F_BE2 + i] = be2[ci * K2 + i];
    }
    for (int i = tid; i < K2 * 3; i += THREADS) pf[F_W3 + i] = W3[ci * K2 * 3 + i];
    if (tid < 3) pf[F_B3 + tid] = b3[ci * 3 + tid];
    for (int i = tid; i < TM * 3; i += THREADS)
        pf[F_PTS + i] = points[(size_t)(bIdx * NN + m0) * 3 + i];
    if (tid == 0) {
#pragma unroll
        for (int j = 0; j < 2; j++) {
            asm volatile("mbarrier.init.shared.b64 [%0], 1;"
                         :: "r"(sbase + MBF_OFF + 8u * j) : "memory");
            asm volatile("mbarrier.init.shared.b64 [%0], 16;"
                         :: "r"(sbase + MBE_OFF + 8u * j) : "memory");
        }
    }
    __syncthreads();

    const __half* Wsrc = g_W2C + (size_t)ci * NCH * K2 * BROWH;
    if (tid == 0) {   // kick off B chunks 0,1 into slots 0,1 (overlaps prologue)
#pragma unroll
        for (int j = 0; j < 2; j++) {
            const uint32_t mb = sbase + MBF_OFF + 8u * j;
            expect_tx(mb, BCHUNK);
            bulk_in(sbase + B0_OFF + (uint32_t)BCHUNK * j,
                    Wsrc + (size_t)j * K2 * BROWH, BCHUNK, mb);
        }
    }

    // ---- LN1 stats (mu, rstd); 16 warps x 8 points ----
#pragma unroll 1
    for (int p = 0; p < 8; p++) {
        const int m = wid * 8 + p;
        const float p0 = pf[F_PTS + m * 3 + 0];
        const float p1 = pf[F_PTS + m * 3 + 1];
        const float p2 = pf[F_PTS + m * 3 + 2];
        float s = 0.f, s2 = 0.f;
#pragma unroll
        for (int q = 0; q < 4; q++) {
            const int k = lane * 16 + q * 4;
            const float4 a0 = *(const float4*)(pf + F_W1 + k);
            const float4 a1 = *(const float4*)(pf + F_W1 + 512 + k);
            const float4 a2 = *(const float4*)(pf + F_W1 + 1024 + k);
            const float4 bb = *(const float4*)(pf + F_B1 + k);
            const float h0 = fmaf(p0, a0.x, fmaf(p1, a1.x, fmaf(p2, a2.x, bb.x)));
            const float h1v= fmaf(p0, a0.y, fmaf(p1, a1.y, fmaf(p2, a2.y, bb.y)));
            const float h2 = fmaf(p0, a0.z, fmaf(p1, a1.z, fmaf(p2, a2.z, bb.z)));
            const float h3 = fmaf(p0, a0.w, fmaf(p1, a1.w, fmaf(p2, a2.w, bb.w)));
            s += h0 + h1v + h2 + h3;
            s2 = fmaf(h0, h0, s2); s2 = fmaf(h1v, h1v, s2);
            s2 = fmaf(h2, h2, s2); s2 = fmaf(h3, h3, s2);
        }
        s  = warp_sum(s);
        s2 = warp_sum(s2);
        if (lane == 0) {
            const float mu = s * (1.f / HH);
            pf[F_MU + m] = mu;
            pf[F_RS + m] = rsqrtf(s2 * (1.f / HH) - mu * mu + EPSLN);
        }
    }
    __syncthreads();

    // ---- produce ENTIRE A tile (128 x 512 fp16) into smem, once ----
    {
        const int am = tid >> 2, t3 = tid & 3;
        const float AP0 = pf[F_PTS + am * 3 + 0];
        const float AP1 = pf[F_PTS + am * 3 + 1];
        const float AP2 = pf[F_PTS + am * 3 + 2];
        const float AMU = pf[F_MU + am];
        const float ARS = pf[F_RS + am];
        const uint32_t rowb = sbase + A_OFF + (uint32_t)(am * AROWB + t3 * 32);
#pragma unroll 1
        for (int cc = 0; cc < NCH; cc++) {
            const uint32_t base = rowb + (uint32_t)(cc * 128);
#pragma unroll
            for (int half = 0; half < 2; half++) {
                uint32_t u[4];
#pragma unroll
                for (int q = 0; q < 2; q++) {
                    const int k = cc * KC + t3 * 16 + half * 8 + q * 4;
                    const float4 a0 = *(const float4*)(pf + F_W1 + k);
                    const float4 a1 = *(const float4*)(pf + F_W1 + 512 + k);
                    const float4 a2 = *(const float4*)(pf + F_W1 + 1024 + k);
                    const float4 bbv= *(const float4*)(pf + F_B1 + k);
                    const float4 gg = *(const float4*)(pf + F_G1 + k);
                    const float4 ee = *(const float4*)(pf + F_BE1 + k);
                    float y0 = (fmaf(AP0, a0.x, fmaf(AP1, a1.x, fmaf(AP2, a2.x, bbv.x))) - AMU) * ARS;
                    float y1 = (fmaf(AP0, a0.y, fmaf(AP1, a1.y, fmaf(AP2, a2.y, bbv.y))) - AMU) * ARS;
                    float y2 = (fmaf(AP0, a0.z, fmaf(AP1, a1.z, fmaf(AP2, a2.z, bbv.z))) - AMU) * ARS;
                    float y3 = (fmaf(AP0, a0.w, fmaf(AP1, a1.w, fmaf(AP2, a2.w, bbv.w))) - AMU) * ARS;
                    y0 = fmaf(y0, gg.x, ee.x); y1 = fmaf(y1, gg.y, ee.y);
                    y2 = fmaf(y2, gg.z, ee.z); y3 = fmaf(y3, gg.w, ee.w);
                    y0 = y0 >= 0.f ? y0 : SLOPE * y0;
                    y1 = y1 >= 0.f ? y1 : SLOPE * y1;
                    y2 = y2 >= 0.f ? y2 : SLOPE * y2;
                    y3 = y3 >= 0.f ? y3 : SLOPE * y3;
                    const __half2 h01 = __floats2half2_rn(y0, y1);
                    const __half2 h23 = __floats2half2_rn(y2, y3);
                    u[q * 2 + 0] = *(const uint32_t*)&h01;
                    u[q * 2 + 1] = *(const uint32_t*)&h23;
                }
                asm volatile("st.shared.v4.b32 [%0], {%1,%2,%3,%4};"
                             :: "r"(base + (uint32_t)(half * 16)),
                                "r"(u[0]), "r"(u[1]), "r"(u[2]), "r"(u[3]));
            }
        }
    }
    __syncthreads();   // A fully visible; mainloop has NO further CTA barriers

    // warp tile: wm = wid>>2 (rows wm*32..), wn = wid&3 (cols wn*64..)
    const int wm = wid >> 2, wn = wid & 3;
    const int grp = lane >> 3, r8 = lane & 7;
    const uint32_t a_lane = sbase + A_OFF
                          + (uint32_t)((r8 + ((grp & 1) << 3) + wm * 32) * AROWB
                                       + (grp >> 1) * 16);
    const uint32_t b_lane = (uint32_t)((r8 + ((grp >> 1) << 3) + wn * 64) * 144
                                       + (grp & 1) * 16);

    float acc[64];
#pragma unroll
    for (int i = 0; i < 64; i++) acc[i] = 0.f;

#pragma unroll 1
    for (int c = 0; c < NCH; c++) {
        const int s = c & 1;
        const uint32_t par = (uint32_t)((c >> 1) & 1);
        mbar_wait(sbase + MBF_OFF + 8u * s, par);

        const uint32_t abase = a_lane + (uint32_t)(c * 128);
        const uint32_t bbase = sbase + B0_OFF + (uint32_t)BCHUNK * s + b_lane;
#pragma unroll
        for (int ks = 0; ks < 4; ks++) {
            const uint32_t koff = (uint32_t)(ks * 32);
            uint32_t af[2][4], bf[4][4];
#pragma unroll
            for (int mt = 0; mt < 2; mt++)
                ldsm4(af[mt], abase + (uint32_t)(mt * 16 * AROWB) + koff);
#pragma unroll
            for (int p = 0; p < 4; p++)
                ldsm4(bf[p], bbase + (uint32_t)(p * 2304) + koff);
#pragma unroll
            for (int mt = 0; mt < 2; mt++)
#pragma unroll
                for (int p = 0; p < 4; p++) {
                    mma_f16(&acc[mt * 32 + (2 * p) * 4],     af[mt], bf[p][0], bf[p][1]);
                    mma_f16(&acc[mt * 32 + (2 * p + 1) * 4], af[mt], bf[p][2], bf[p][3]);
                }
        }
        if (lane == 0) mbar_arrive(sbase + MBE_OFF + 8u * s);
        if (tid == 0 && c + 2 < NCH) {
            mbar_wait(sbase + MBE_OFF + 8u * s, par);   // all 16 warps done with slot
            const uint32_t mb = sbase + MBF_OFF + 8u * s;
            expect_tx(mb, BCHUNK);
            bulk_in(sbase + B0_OFF + (uint32_t)BCHUNK * s,
                    Wsrc + (size_t)(c + 2) * K2 * BROWH, BCHUNK, mb);
        }
    }
    __syncthreads();   // all warps done before overwriting A/B region with C

    // ---- store acc to smem C [128][CSTR] ----
    {
        const int rbase = wm * 32 + (lane >> 2);
        const int cbase = wn * 64 + 2 * (lane & 3);
#pragma unroll
        for (int mt = 0; mt < 2; mt++)
#pragma unroll
            for (int nt = 0; nt < 8; nt++) {
                const float* a4 = &acc[mt * 32 + nt * 4];
                const int r0 = rbase + mt * 16, cc = cbase + nt * 8;
                *(float2*)(csm + r0 * CSTR + cc)       = make_float2(a4[0], a4[1]);
                *(float2*)(csm + (r0 + 8) * CSTR + cc) = make_float2(a4[2], a4[3]);
            }
    }
    __syncthreads();

    // ---- epilogue: bias2 + LN2 + lrelu + GEMM3 (N=3); 16 warps x 8 rows ----
#pragma unroll 1
    for (int rr = 0; rr < 8; rr++) {
        const int m = wid * 8 + rr;
        float fv[8];
        float s = 0.f, s2 = 0.f;
#pragma unroll
        for (int j = 0; j < 8; j++) {
            const int n = lane + 32 * j;
            fv[j] = csm[m * CSTR + n] + pf[F_B2 + n];
            s += fv[j];
            s2 = fmaf(fv[j], fv[j], s2);
        }
        s  = warp_sum(s);
        s2 = warp_sum(s2);
        const float mu  = s * (1.f / K2);
        const float inv = rsqrtf(s2 * (1.f / K2) - mu * mu + EPSLN);
        float o0 = 0.f, o1 = 0.f, o2 = 0.f;
#pragma unroll
        for (int j = 0; j < 8; j++) {
            const int n = lane + 32 * j;
            float y = (fv[j] - mu) * inv * pf[F_G2 + n] + pf[F_BE2 + n];
            y = y >= 0.f ? y : SLOPE * y;
            o0 = fmaf(y, pf[F_W3 + n * 3 + 0], o0);
            o1 = fmaf(y, pf[F_W3 + n * 3 + 1], o1);
            o2 = fmaf(y, pf[F_W3 + n * 3 + 2], o2);
        }
        o0 = warp_sum(o0); o1 = warp_sum(o1); o2 = warp_sum(o2);
        if (lane == 0) {
            float* op = out + (size_t)(bIdx * NN + m0 + m) * 3;
            op[0] = o0 + pf[F_B3 + 0];
            op[1] = o1 + pf[F_B3 + 1];
            op[2] = o2 + pf[F_B3 + 2];
        }
    }
}

extern "C" void kernel_launch(void* const* d_in, const int* in_sizes, int n_in,
                              void* d_out, int out_size)
{
    const float* points = (const float*)d_in[0];
    const int*   cat    = (const int*)  d_in[1];
    const float* W1     = (const float*)d_in[2];
    const float* b1     = (const float*)d_in[3];
    const float* g1     = (const float*)d_in[4];
    const float* be1    = (const float*)d_in[5];
    const float* W2     = (const float*)d_in[6];
    const float* b2     = (const float*)d_in[7];
    const float* g2     = (const float*)d_in[8];
    const float* be2    = (const float*)d_in[9];
    const float* W3     = (const float*)d_in[10];
    const float* b3     = (const float*)d_in[11];
    float* out = (float*)d_out;

    cudaFuncSetAttribute(shape_prior_mma,
                         cudaFuncAttributeMaxDynamicSharedMemorySize, SMEM_TOTAL);

    pack_w2<<<dim3(HH / 32, K2 / 32, NE), dim3(32, 8)>>>(W2);
    shape_prior_mma<<<dim3(NN / TM, BB), THREADS, SMEM_TOTAL>>>(
        points, cat, W1, b1, g1, be1, b2, g2, be2, W3, b3, out);
}

// round 9
// speedup vs baseline: 3.0026x; 2.4113x over previous
#include <cuda_runtime.h>
#include <cuda_fp16.h>
#include <cstdint>

#define BB      32
#define NN      8192
#define HH      512
#define K2      256
#define TM      128
#define THREADS 512
#define EPSLN   1e-5f
#define SLOPE   0.2f
#define KC      64
#define NCH     (HH / KC)       // 8 k-chunks
#define NE      10

// B row: 64 fp16 (128 B) + 16 B pad = 144 B (72 halves)
#define BROWH   72
#define BCHUNK  (K2 * 144)              // 36864 B per chunk

// A tile in smem: 128 rows x (512 fp16 = 1024 B + 16 pad) = 1040 B stride
#define AROWB   1040
#define A_SIZE  (TM * AROWB)            // 133120 B

__device__ __half g_W2C[(size_t)NE * NCH * K2 * BROWH];
// per-expert LN1 closed-form constants:
// M00,M01,M02,M11,M12,M22, v0,v1,v2, S0,S1,S2, Sb, sb2  (16-padded)
__device__ float g_LN1[NE * 16];

// ---------------- smem layout (bytes) ----------------
#define A_OFF  0u
#define B0_OFF 133120u                  // 2 x 36864 -> ends 206848
#define P_OFF  206848u
#define F_W1    0             // [3][512]
#define F_B1    1536
#define F_G1    2048
#define F_BE1   2560
#define F_B2    3072
#define F_G2    3328
#define F_BE2   3584
#define F_W3    3840          // [256][3]
#define F_B3    4608
#define F_PTS   4612          // [128][3]
#define F_MU    4996
#define F_RS    5124
#define F_LC    5252          // 16 LN1 constants
#define F_END   5268
#define MBF_OFF (P_OFF + F_END * 4)    // 227920: 2 x full
#define MBE_OFF (MBF_OFF + 16)         // 2 x empty
#define SMEM_TOTAL (MBE_OFF + 16)      // 227952 B
// epilogue partial buffers alias the dead B ring (float idx rel. to B0_OFF):
#define E_S     0      // [128][4]
#define E_S2    512    // [128][4]
#define E_O     1024   // [128][4][3]

__device__ __forceinline__ uint32_t smem_u32(const void* p) {
    uint32_t a;
    asm("{ .reg .u64 t; cvta.to.shared.u64 t, %1; cvt.u32.u64 %0, t; }" : "=r"(a) : "l"(p));
    return a;
}
__device__ __forceinline__ float warp_sum(float v) {
#pragma unroll
    for (int o = 16; o; o >>= 1) v += __shfl_xor_sync(0xffffffffu, v, o);
    return v;
}
__device__ __forceinline__ void ldsm4(uint32_t* r, uint32_t addr) {
    asm volatile("ldmatrix.sync.aligned.m8n8.x4.shared.b16 {%0,%1,%2,%3}, [%4];"
                 : "=r"(r[0]), "=r"(r[1]), "=r"(r[2]), "=r"(r[3]) : "r"(addr));
}
__device__ __forceinline__ void mma_f16(float* c, const uint32_t* a, uint32_t b0, uint32_t b1) {
    asm volatile("mma.sync.aligned.m16n8k16.row.col.f32.f16.f16.f32 "
                 "{%0,%1,%2,%3}, {%4,%5,%6,%7}, {%8,%9}, {%0,%1,%2,%3};"
                 : "+f"(c[0]), "+f"(c[1]), "+f"(c[2]), "+f"(c[3])
                 : "r"(a[0]), "r"(a[1]), "r"(a[2]), "r"(a[3]), "r"(b0), "r"(b1));
}
__device__ __forceinline__ void mbar_wait(uint32_t addr, uint32_t parity) {
    asm volatile(
        "{\n\t.reg .pred P;\n\t"
        "WL_%=:\n\t"
        "mbarrier.try_wait.parity.acquire.cta.shared::cta.b64 P, [%0], %1, 0x989680;\n\t"
        "@P bra.uni WD_%=;\n\t"
        "bra.uni WL_%=;\n\t"
        "WD_%=:\n\t}"
        :: "r"(addr), "r"(parity) : "memory");
}
__device__ __forceinline__ void bulk_in(uint32_t dst, const void* src, uint32_t bytes,
                                        uint32_t mbar) {
    asm volatile(
        "cp.async.bulk.shared::cluster.global.mbarrier::complete_tx::bytes "
        "[%0], [%1], %2, [%3];"
        :: "r"(dst), "l"(src), "r"(bytes), "r"(mbar) : "memory");
}
__device__ __forceinline__ void expect_tx(uint32_t mbar, uint32_t bytes) {
    asm volatile("mbarrier.arrive.expect_tx.shared.b64 _, [%0], %1;"
                 :: "r"(mbar), "r"(bytes) : "memory");
}
__device__ __forceinline__ void mbar_arrive(uint32_t mbar) {
    asm volatile("mbarrier.arrive.shared.b64 _, [%0];" :: "r"(mbar) : "memory");
}
__device__ __forceinline__ float lrelu(float y) { return y >= 0.f ? y : SLOPE * y; }

// ------------- W2 pack: transpose + fp16 + chunk image -------------
__global__ void pack_w2(const float* __restrict__ W2) {
    __shared__ float t[32][33];
    const int e  = blockIdx.z;
    const int kb = blockIdx.x * 32, nb = blockIdx.y * 32;
    const int tx = threadIdx.x, ty = threadIdx.y;
    const float* src = W2 + e * HH * K2;
#pragma unroll
    for (int r = 0; r < 32; r += 8)
        t[ty + r][tx] = src[(kb + ty + r) * K2 + nb + tx];
    __syncthreads();
    const int ch = kb >> 6, k0 = kb & 63;
    __half* dst = g_W2C + ((size_t)(e * NCH + ch) * K2) * BROWH;
#pragma unroll
    for (int r = 0; r < 32; r += 8)
        dst[(size_t)(nb + ty + r) * BROWH + k0 + tx] = __float2half_rn(t[tx][ty + r]);
}

// ------------- LN1 closed-form constants per expert -------------
__global__ void pack_ln1(const float* __restrict__ W1, const float* __restrict__ b1) {
    __shared__ float red[16][14];
    const int e = blockIdx.x, tid = threadIdx.x;   // 512 threads
    const float* w = W1 + e * 3 * HH;
    const float w0 = w[tid], w1 = w[HH + tid], w2 = w[2 * HH + tid];
    const float bb = b1[e * HH + tid];
    float vals[14] = { w0*w0, w0*w1, w0*w2, w1*w1, w1*w2, w2*w2,
                       w0*bb, w1*bb, w2*bb, w0, w1, w2, bb, bb*bb };
#pragma unroll
    for (int i = 0; i < 14; i++) vals[i] = warp_sum(vals[i]);
    const int wid = tid >> 5, lane = tid & 31;
    if (lane == 0)
#pragma unroll
        for (int i = 0; i < 14; i++) red[wid][i] = vals[i];
    __syncthreads();
    if (tid < 14) {
        float s = 0.f;
#pragma unroll
        for (int wq = 0; wq < 16; wq++) s += red[wq][tid];
        g_LN1[e * 16 + tid] = s;
    }
    if (tid >= 14 && tid < 16) g_LN1[e * 16 + tid] = 0.f;
}

extern __shared__ char smem_raw[];

__global__ __launch_bounds__(THREADS, 1)
void shape_prior_mma(const float* __restrict__ points, const int* __restrict__ cat,
                     const float* __restrict__ W1, const float* __restrict__ b1,
                     const float* __restrict__ g1, const float* __restrict__ be1,
                     const float* __restrict__ b2, const float* __restrict__ g2,
                     const float* __restrict__ be2,
                     const float* __restrict__ W3, const float* __restrict__ b3,
                     float* __restrict__ out)
{
    float* pf = (float*)(smem_raw + P_OFF);
    float* ep = (float*)(smem_raw + B0_OFF);   // epilogue partials (alias B ring)
    const int tid  = threadIdx.x;
    const int wid  = tid >> 5;
    const int lane = tid & 31;
    const int bIdx = blockIdx.y;
    const int m0   = blockIdx.x * TM;
    const int ci   = cat[bIdx];
    const uint32_t sbase = smem_u32(smem_raw);

    // ---- stage per-expert params + points ----
    for (int i = tid; i < 3 * HH; i += THREADS) pf[F_W1 + i] = W1[ci * 3 * HH + i];
    for (int i = tid; i < HH; i += THREADS) {
        pf[F_B1  + i] = b1 [ci * HH + i];
        pf[F_G1  + i] = g1 [ci * HH + i];
        pf[F_BE1 + i] = be1[ci * HH + i];
    }
    for (int i = tid; i < K2; i += THREADS) {
        pf[F_B2  + i] = b2 [ci * K2 + i];
        pf[F_G2  + i] = g2 [ci * K2 + i];
        pf[F_BE2 + i] = be2[ci * K2 + i];
    }
    for (int i = tid; i < K2 * 3; i += THREADS) pf[F_W3 + i] = W3[ci * K2 * 3 + i];
    if (tid < 3) pf[F_B3 + tid] = b3[ci * 3 + tid];
    if (tid < 16) pf[F_LC + tid] = g_LN1[ci * 16 + tid];
    for (int i = tid; i < TM * 3; i += THREADS)
        pf[F_PTS + i] = points[(size_t)(bIdx * NN + m0) * 3 + i];
    if (tid == 0) {
#pragma unroll
        for (int j = 0; j < 2; j++) {
            asm volatile("mbarrier.init.shared.b64 [%0], 1;"
                         :: "r"(sbase + MBF_OFF + 8u * j) : "memory");
            asm volatile("mbarrier.init.shared.b64 [%0], 16;"
                         :: "r"(sbase + MBE_OFF + 8u * j) : "memory");
        }
    }
    __syncthreads();

    const __half* Wsrc = g_W2C + (size_t)ci * NCH * K2 * BROWH;
    if (tid == 0) {   // kick off B chunks 0,1 (overlaps prologue)
#pragma unroll
        for (int j = 0; j < 2; j++) {
            const uint32_t mb = sbase + MBF_OFF + 8u * j;
            expect_tx(mb, BCHUNK);
            bulk_in(sbase + B0_OFF + (uint32_t)BCHUNK * j,
                    Wsrc + (size_t)j * K2 * BROWH, BCHUNK, mb);
        }
    }

    // ---- LN1 stats via closed form: O(1) per point ----
    if (tid < TM) {
        const float p0 = pf[F_PTS + tid * 3 + 0];
        const float p1 = pf[F_PTS + tid * 3 + 1];
        const float p2 = pf[F_PTS + tid * 3 + 2];
        const float* L = pf + F_LC;
        const float sum = fmaf(p0, L[9], fmaf(p1, L[10], fmaf(p2, L[11], L[12])));
        float sq = L[13];
        sq = fmaf(p0 * p0, L[0], sq);
        sq = fmaf(2.f * p0 * p1, L[1], sq);
        sq = fmaf(2.f * p0 * p2, L[2], sq);
        sq = fmaf(p1 * p1, L[3], sq);
        sq = fmaf(2.f * p1 * p2, L[4], sq);
        sq = fmaf(p2 * p2, L[5], sq);
        sq = fmaf(2.f * p0, L[6], sq);
        sq = fmaf(2.f * p1, L[7], sq);
        sq = fmaf(2.f * p2, L[8], sq);
        const float mu = sum * (1.f / HH);
        pf[F_MU + tid] = mu;
        pf[F_RS + tid] = rsqrtf(sq * (1.f / HH) - mu * mu + EPSLN);
    }
    __syncthreads();

    // ---- produce full A tile: thread owns 2 adjacent columns, loops points ----
    {
        const int mh = tid >> 8, pr = tid & 255;
        const int c0 = 2 * pr;
        const float wa0 = pf[F_W1 + c0],        wb0 = pf[F_W1 + c0 + 1];
        const float wa1 = pf[F_W1 + 512 + c0],  wb1 = pf[F_W1 + 513 + c0];
        const float wa2 = pf[F_W1 + 1024 + c0], wb2 = pf[F_W1 + 1025 + c0];
        const float ba  = pf[F_B1 + c0],  bbv = pf[F_B1 + c0 + 1];
        const float ga  = pf[F_G1 + c0],  gb  = pf[F_G1 + c0 + 1];
        const float ea  = pf[F_BE1 + c0], eb  = pf[F_BE1 + c0 + 1];
        uint32_t dst = sbase + A_OFF + (uint32_t)((mh * 64) * AROWB + pr * 4);
#pragma unroll 4
        for (int mi = 0; mi < 64; mi++) {
            const int m = mh * 64 + mi;
            const float p0 = pf[F_PTS + m * 3 + 0];
            const float p1 = pf[F_PTS + m * 3 + 1];
            const float p2 = pf[F_PTS + m * 3 + 2];
            const float mu = pf[F_MU + m], rs = pf[F_RS + m];
            const float x0 = fmaf(p0, wa0, fmaf(p1, wa1, fmaf(p2, wa2, ba)));
            const float x1 = fmaf(p0, wb0, fmaf(p1, wb1, fmaf(p2, wb2, bbv)));
            const float y0 = lrelu(fmaf((x0 - mu) * rs, ga, ea));
            const float y1 = lrelu(fmaf((x1 - mu) * rs, gb, eb));
            const __half2 h = __floats2half2_rn(y0, y1);
            asm volatile("st.shared.b32 [%0], %1;"
                         :: "r"(dst), "r"(*(const uint32_t*)&h));
            dst += AROWB;
        }
    }
    __syncthreads();   // A visible; mainloop has no CTA barriers

    // warp tile: wm = wid>>2 (rows wm*32..), wn = wid&3 (cols wn*64..)
    const int wm = wid >> 2, wn = wid & 3;
    const int grp = lane >> 3, r8 = lane & 7;
    const uint32_t a_lane = sbase + A_OFF
                          + (uint32_t)((r8 + ((grp & 1) << 3) + wm * 32) * AROWB
                                       + (grp >> 1) * 16);
    const uint32_t b_lane = (uint32_t)((r8 + ((grp >> 1) << 3) + wn * 64) * 144
                                       + (grp & 1) * 16);

    float acc[64];
#pragma unroll
    for (int i = 0; i < 64; i++) acc[i] = 0.f;

#pragma unroll 1
    for (int c = 0; c < NCH; c++) {
        const int s = c & 1;
        const uint32_t par = (uint32_t)((c >> 1) & 1);
        mbar_wait(sbase + MBF_OFF + 8u * s, par);

        const uint32_t abase = a_lane + (uint32_t)(c * 128);
        const uint32_t bbase = sbase + B0_OFF + (uint32_t)BCHUNK * s + b_lane;
#pragma unroll
        for (int ks = 0; ks < 4; ks++) {
            const uint32_t koff = (uint32_t)(ks * 32);
            uint32_t af[2][4], bf[4][4];
#pragma unroll
            for (int mt = 0; mt < 2; mt++)
                ldsm4(af[mt], abase + (uint32_t)(mt * 16 * AROWB) + koff);
#pragma unroll
            for (int p = 0; p < 4; p++)
                ldsm4(bf[p], bbase + (uint32_t)(p * 2304) + koff);
#pragma unroll
            for (int mt = 0; mt < 2; mt++)
#pragma unroll
                for (int p = 0; p < 4; p++) {
                    mma_f16(&acc[mt * 32 + (2 * p) * 4],     af[mt], bf[p][0], bf[p][1]);
                    mma_f16(&acc[mt * 32 + (2 * p + 1) * 4], af[mt], bf[p][2], bf[p][3]);
                }
        }
        if (lane == 0) mbar_arrive(sbase + MBE_OFF + 8u * s);
        if (tid == 0 && c + 2 < NCH) {
            mbar_wait(sbase + MBE_OFF + 8u * s, par);
            const uint32_t mb = sbase + MBF_OFF + 8u * s;
            expect_tx(mb, BCHUNK);
            bulk_in(sbase + B0_OFF + (uint32_t)BCHUNK * s,
                    Wsrc + (size_t)(c + 2) * K2 * BROWH, BCHUNK, mb);
        }
    }
    __syncthreads();   // mainloop done; B ring dead -> ep aliasing safe

    // ---- epilogue in registers ----
    // thread rows: r[j] = rbase + 8j, j=0..3; rbase = wm*32 + (lane>>2)
    // thread cols (per nt): wn*64 + nt*8 + 2*(lane&3) + {0,1}
    const int rbase = wm * 32 + (lane >> 2);
    {
        float s[4] = {0.f, 0.f, 0.f, 0.f}, q[4] = {0.f, 0.f, 0.f, 0.f};
#pragma unroll
        for (int nt = 0; nt < 8; nt++) {
            const int n = wn * 64 + nt * 8 + 2 * (lane & 3);
            const float2 bv = *(const float2*)(pf + F_B2 + n);
#pragma unroll
            for (int mt = 0; mt < 2; mt++) {
                float* a4 = &acc[mt * 32 + nt * 4];
                a4[0] += bv.x; a4[1] += bv.y; a4[2] += bv.x; a4[3] += bv.y;
                const int j0 = mt * 2, j1 = mt * 2 + 1;
                s[j0] += a4[0] + a4[1];
                q[j0] = fmaf(a4[0], a4[0], fmaf(a4[1], a4[1], q[j0]));
                s[j1] += a4[2] + a4[3];
                q[j1] = fmaf(a4[2], a4[2], fmaf(a4[3], a4[3], q[j1]));
            }
        }
#pragma unroll
        for (int j = 0; j < 4; j++) {
            s[j] += __shfl_xor_sync(0xffffffffu, s[j], 1);
            s[j] += __shfl_xor_sync(0xffffffffu, s[j], 2);
            q[j] += __shfl_xor_sync(0xffffffffu, q[j], 1);
            q[j] += __shfl_xor_sync(0xffffffffu, q[j], 2);
        }
        if ((lane & 3) == 0) {
#pragma unroll
            for (int j = 0; j < 4; j++) {
                const int r = rbase + 8 * j;
                ep[E_S  + r * 4 + wn] = s[j];
                ep[E_S2 + r * 4 + wn] = q[j];
            }
        }
    }
    __syncthreads();

    {
        float mu[4], rs[4];
#pragma unroll
        for (int j = 0; j < 4; j++) {
            const int r = rbase + 8 * j;
            const float4 sv = *(const float4*)(ep + E_S  + r * 4);
            const float4 qv = *(const float4*)(ep + E_S2 + r * 4);
            const float ss = (sv.x + sv.y) + (sv.z + sv.w);
            const float qq = (qv.x + qv.y) + (qv.z + qv.w);
            const float m_ = ss * (1.f / K2);
            mu[j] = m_;
            rs[j] = rsqrtf(qq * (1.f / K2) - m_ * m_ + EPSLN);
        }
        float o0[4] = {0,0,0,0}, o1[4] = {0,0,0,0}, o2[4] = {0,0,0,0};
#pragma unroll
        for (int nt = 0; nt < 8; nt++) {
            const int n = wn * 64 + nt * 8 + 2 * (lane & 3);
            const float2 gv = *(const float2*)(pf + F_G2 + n);
            const float2 ev = *(const float2*)(pf + F_BE2 + n);
            const float w3a0 = pf[F_W3 + n * 3 + 0];
            const float w3a1 = pf[F_W3 + n * 3 + 1];
            const float w3a2 = pf[F_W3 + n * 3 + 2];
            const float w3b0 = pf[F_W3 + n * 3 + 3];
            const float w3b1 = pf[F_W3 + n * 3 + 4];
            const float w3b2 = pf[F_W3 + n * 3 + 5];
#pragma unroll
            for (int mt = 0; mt < 2; mt++) {
                const float* a4 = &acc[mt * 32 + nt * 4];
#pragma unroll
                for (int hh2 = 0; hh2 < 2; hh2++) {   // row half (i>>1)
                    const int j = mt * 2 + hh2;
                    const float ya = lrelu(fmaf((a4[hh2 * 2 + 0] - mu[j]) * rs[j], gv.x, ev.x));
                    const float yb = lrelu(fmaf((a4[hh2 * 2 + 1] - mu[j]) * rs[j], gv.y, ev.y));
                    o0[j] = fmaf(ya, w3a0, fmaf(yb, w3b0, o0[j]));
                    o1[j] = fmaf(ya, w3a1, fmaf(yb, w3b1, o1[j]));
                    o2[j] = fmaf(ya, w3a2, fmaf(yb, w3b2, o2[j]));
                }
            }
        }
#pragma unroll
        for (int j = 0; j < 4; j++) {
            o0[j] += __shfl_xor_sync(0xffffffffu, o0[j], 1);
            o0[j] += __shfl_xor_sync(0xffffffffu, o0[j], 2);
            o1[j] += __shfl_xor_sync(0xffffffffu, o1[j], 1);
            o1[j] += __shfl_xor_sync(0xffffffffu, o1[j], 2);
            o2[j] += __shfl_xor_sync(0xffffffffu, o2[j], 1);
            o2[j] += __shfl_xor_sync(0xffffffffu, o2[j], 2);
        }
        if ((lane & 3) == 0) {
#pragma unroll
            for (int j = 0; j < 4; j++) {
                const int r = rbase + 8 * j;
                ep[E_O + r * 12 + wn * 3 + 0] = o0[j];
                ep[E_O + r * 12 + wn * 3 + 1] = o1[j];
                ep[E_O + r * 12 + wn * 3 + 2] = o2[j];
            }
        }
    }
    __syncthreads();

    if (tid < TM) {
        const int r = tid;
        float v0 = pf[F_B3 + 0], v1 = pf[F_B3 + 1], v2 = pf[F_B3 + 2];
#pragma unroll
        for (int w = 0; w < 4; w++) {
            v0 += ep[E_O + r * 12 + w * 3 + 0];
            v1 += ep[E_O + r * 12 + w * 3 + 1];
            v2 += ep[E_O + r * 12 + w * 3 + 2];
        }
        float* op = out + (size_t)(bIdx * NN + m0 + r) * 3;
        op[0] = v0; op[1] = v1; op[2] = v2;
    }
}

extern "C" void kernel_launch(void* const* d_in, const int* in_sizes, int n_in,
                              void* d_out, int out_size)
{
    const float* points = (const float*)d_in[0];
    const int*   cat    = (const int*)  d_in[1];
    const float* W1     = (const float*)d_in[2];
    const float* b1     = (const float*)d_in[3];
    const float* g1     = (const float*)d_in[4];
    const float* be1    = (const float*)d_in[5];
    const float* W2     = (const float*)d_in[6];
    const float* b2     = (const float*)d_in[7];
    const float* g2     = (const float*)d_in[8];
    const float* be2    = (const float*)d_in[9];
    const float* W3     = (const float*)d_in[10];
    const float* b3     = (const float*)d_in[11];
    float* out = (float*)d_out;

    cudaFuncSetAttribute(shape_prior_mma,
                         cudaFuncAttributeMaxDynamicSharedMemorySize, SMEM_TOTAL);

    pack_w2<<<dim3(HH / 32, K2 / 32, NE), dim3(32, 8)>>>(W2);
    pack_ln1<<<NE, 512>>>(W1, b1);
    shape_prior_mma<<<dim3(NN / TM, BB), THREADS, SMEM_TOTAL>>>(
        points, cat, W1, b1, g1, be1, b2, g2, be2, W3, b3, out);
}